// round 1
// baseline (speedup 1.0000x reference)
#include <cuda_runtime.h>
#include <math.h>

#define N_NODES   50000
#define N_EDGES   600000
#define IN_DIM    64
#define D         128
#define N_LAYERS  8
#define N_ETYPES  44
#define N_MENTIONS 100000
#define N_VARS    20000
#define OUT_DIM   100

// ---------------- scratch (device globals; no allocation allowed) ----------------
__device__ float g_h[N_NODES * D];          // node state
__device__ float g_t[N_NODES * D];          // encoder intermediate / decoder hidden
__device__ float g_acc[N_NODES * D];        // per-layer segment-sum accumulator
__device__ float g_PQ[N_NODES * 512];       // [n][0:256]=P (dst part), [n][256:512]=Q (src part)
__device__ float g_R[N_LAYERS * N_ETYPES * 256]; // per-etype bias incl. b1
__device__ float g_vsum[N_VARS * D];
__device__ float g_vcnt[N_VARS];
__device__ float g_vrep[N_VARS * D];

// ---------------- generic tiled SGEMM: C = act(A@B + bias) ----------------
// A[M,K] lda, B[K,N] ldb, C[M,N] ldc. K must be a multiple of 16. act: 0=none, 1=relu.
__global__ void sgemm_kernel(const float* __restrict__ A, int lda,
                             const float* __restrict__ B, int ldb,
                             const float* __restrict__ bias,
                             float* __restrict__ C, int ldc,
                             int M, int N, int K, int act)
{
    __shared__ __align__(16) float As[16][68];  // As[k][m], padded
    __shared__ __align__(16) float Bs[16][64];  // Bs[k][n]
    const int tid = threadIdx.x;
    const int m0 = blockIdx.y * 64, n0 = blockIdx.x * 64;
    const int ty = tid >> 4, tx = tid & 15;

    float acc[4][4];
#pragma unroll
    for (int i = 0; i < 4; i++)
#pragma unroll
        for (int j = 0; j < 4; j++) acc[i][j] = 0.f;

    for (int k0 = 0; k0 < K; k0 += 16) {
        // load A tile 64x16 (store transposed)
        {
            int r = tid >> 4;     // 0..15
            int c = tid & 15;     // 0..15
#pragma unroll
            for (int p = 0; p < 4; p++) {
                int m = m0 + p * 16 + r;
                float v = (m < M) ? A[(size_t)m * lda + k0 + c] : 0.f;
                As[c][p * 16 + r] = v;
            }
        }
        // load B tile 16x64
        {
            int r = tid >> 6;     // 0..3
            int c = tid & 63;     // 0..63
#pragma unroll
            for (int p = 0; p < 4; p++) {
                int k = k0 + p * 4 + r;
                int n = n0 + c;
                Bs[p * 4 + r][c] = (n < N) ? B[(size_t)k * ldb + n] : 0.f;
            }
        }
        __syncthreads();
#pragma unroll
        for (int kk = 0; kk < 16; kk++) {
            float4 a4 = *(const float4*)&As[kk][ty * 4];
            float4 b4 = *(const float4*)&Bs[kk][tx * 4];
            acc[0][0] += a4.x * b4.x; acc[0][1] += a4.x * b4.y; acc[0][2] += a4.x * b4.z; acc[0][3] += a4.x * b4.w;
            acc[1][0] += a4.y * b4.x; acc[1][1] += a4.y * b4.y; acc[1][2] += a4.y * b4.z; acc[1][3] += a4.y * b4.w;
            acc[2][0] += a4.z * b4.x; acc[2][1] += a4.z * b4.y; acc[2][2] += a4.z * b4.z; acc[2][3] += a4.z * b4.w;
            acc[3][0] += a4.w * b4.x; acc[3][1] += a4.w * b4.y; acc[3][2] += a4.w * b4.z; acc[3][3] += a4.w * b4.w;
        }
        __syncthreads();
    }
#pragma unroll
    for (int i = 0; i < 4; i++) {
        int m = m0 + ty * 4 + i;
        if (m >= M) continue;
#pragma unroll
        for (int j = 0; j < 4; j++) {
            int n = n0 + tx * 4 + j;
            if (n >= N) continue;
            float v = acc[i][j] + (bias ? bias[n] : 0.f);
            if (act == 1) v = fmaxf(v, 0.f);
            C[(size_t)m * ldc + n] = v;
        }
    }
}

// ---------------- per-etype R table: R[l][e][:] = edge_emb[l][e] @ W1[256:384,:] + b1 ----------------
__global__ void r_kernel(const float* __restrict__ edge_emb,   // [8][44][128]
                         const float* __restrict__ mlp_W1,     // [8][384][256]
                         const float* __restrict__ mlp_b1,     // [8][256]
                         float* __restrict__ R)                // [8][44][256]
{
    int l = blockIdx.y, e = blockIdx.x, j = threadIdx.x;  // 256 threads
    __shared__ float emb[128];
    if (j < 128) emb[j] = edge_emb[(l * N_ETYPES + e) * 128 + j];
    __syncthreads();
    const float* W = mlp_W1 + ((size_t)l * 384 + 256) * 256;
    float s = mlp_b1[l * 256 + j];
#pragma unroll 8
    for (int k = 0; k < 128; k++) s += emb[k] * W[k * 256 + j];
    R[((size_t)l * N_ETYPES + e) * 256 + j] = s;
}

// ---------------- edge kernel: z = relu(P[dst]+Q[src]+R[et]); acc[dst] += z@W2 + b2 ----------------
// persistent blocks; W2 (256x128) resident in smem; 32 edges per tile; 4x4 microtiles.
#define TE 32
__global__ void edge_kernel(const int* __restrict__ edges,   // [2][E]
                            const int* __restrict__ elab,
                            const float* __restrict__ Rl,    // [44][256]
                            const float* __restrict__ W2l,   // [256][128]
                            const float* __restrict__ b2l)   // [128]
{
    extern __shared__ __align__(16) float sm[];
    float* W2s = sm;                  // 256*128
    float* Zs  = sm + 256 * 128;      // [k][e] stride 33 -> 256*33
    __shared__ int s_src[TE], s_dst[TE], s_lab[TE];

    const int tid = threadIdx.x;      // 256
    for (int i = tid; i < 256 * 128; i += 256) W2s[i] = W2l[i];

    const int eg = tid >> 5;          // edge group 0..7  (edges eg*4..eg*4+3)
    const int jg = tid & 31;          // out group  0..31 (chans jg*4..jg*4+3)
    const float bb0 = b2l[jg * 4 + 0], bb1 = b2l[jg * 4 + 1];
    const float bb2 = b2l[jg * 4 + 2], bb3 = b2l[jg * 4 + 3];
    __syncthreads();

    for (int base = blockIdx.x * TE; base < N_EDGES; base += gridDim.x * TE) {
        if (tid < TE) {
            s_src[tid] = edges[base + tid];
            s_dst[tid] = edges[N_EDGES + base + tid];
            s_lab[tid] = elab[base + tid];
        }
        __syncthreads();
        // Z phase: thread tid owns k=tid; N_EDGES % TE == 0 so all 32 edges valid
#pragma unroll 8
        for (int e = 0; e < TE; e++) {
            int dn = s_dst[e], sn = s_src[e], lb = s_lab[e];
            float z = g_PQ[dn * 512 + tid] + g_PQ[sn * 512 + 256 + tid] + Rl[lb * 256 + tid];
            Zs[tid * 33 + e] = fmaxf(z, 0.f);
        }
        __syncthreads();
        // GEMM phase: OUT[32][128] = Z[32][256] @ W2[256][128]
        float a[4][4];
#pragma unroll
        for (int i = 0; i < 4; i++) { a[i][0] = bb0; a[i][1] = bb1; a[i][2] = bb2; a[i][3] = bb3; }
        const float* Zc = Zs + eg * 4;
#pragma unroll 8
        for (int k = 0; k < 256; k++) {
            float4 w = *(const float4*)&W2s[k * 128 + jg * 4];
            float z0 = Zc[k * 33 + 0];
            float z1 = Zc[k * 33 + 1];
            float z2 = Zc[k * 33 + 2];
            float z3 = Zc[k * 33 + 3];
            a[0][0] += z0 * w.x; a[0][1] += z0 * w.y; a[0][2] += z0 * w.z; a[0][3] += z0 * w.w;
            a[1][0] += z1 * w.x; a[1][1] += z1 * w.y; a[1][2] += z1 * w.z; a[1][3] += z1 * w.w;
            a[2][0] += z2 * w.x; a[2][1] += z2 * w.y; a[2][2] += z2 * w.z; a[2][3] += z2 * w.w;
            a[3][0] += z3 * w.x; a[3][1] += z3 * w.y; a[3][2] += z3 * w.z; a[3][3] += z3 * w.w;
        }
#pragma unroll
        for (int i = 0; i < 4; i++) {
            int dn = s_dst[eg * 4 + i];
            float* p = g_acc + dn * 128 + jg * 4;
            atomicAdd(p + 0, a[i][0]);
            atomicAdd(p + 1, a[i][1]);
            atomicAdd(p + 2, a[i][2]);
            atomicAdd(p + 3, a[i][3]);
        }
        __syncthreads();
    }
}

// ---------------- small elementwise kernels ----------------
__global__ void zero_kernel(float* p, int n) {
    int i = blockIdx.x * blockDim.x + threadIdx.x;
    if (i < n) p[i] = 0.f;
}

__global__ void gelu_kernel(const float* __restrict__ in, float* __restrict__ out, int n) {
    int i = blockIdx.x * blockDim.x + threadIdx.x;
    if (i < n) {
        float x = in[i];
        out[i] = 0.5f * x * (1.f + erff(x * 0.70710678118654752f));
    }
}

__global__ void scatter_kernel(const int* __restrict__ vg, const int* __restrict__ vs) {
    int i = blockIdx.x * blockDim.x + threadIdx.x;
    if (i >= N_MENTIONS * D) return;
    int m = i >> 7, c = i & 127;
    int v = vs[m], n = vg[m];
    atomicAdd(&g_vsum[v * D + c], g_h[n * D + c]);
    if (c == 0) atomicAdd(&g_vcnt[v], 1.0f);
}

__global__ void vrep_kernel() {
    int i = blockIdx.x * blockDim.x + threadIdx.x;
    if (i >= N_VARS * D) return;
    int v = i >> 7;
    g_vrep[i] = g_vsum[i] / fmaxf(g_vcnt[v], 1.0f);
}

// ---------------- host ----------------
static void launch_sgemm(const float* A, int lda, const float* B, int ldb, const float* bias,
                         float* C, int ldc, int M, int N, int K, int act)
{
    dim3 grid((N + 63) / 64, (M + 63) / 64);
    sgemm_kernel<<<grid, 256>>>(A, lda, B, ldb, bias, C, ldc, M, N, K, act);
}

extern "C" void kernel_launch(void* const* d_in, const int* in_sizes, int n_in,
                              void* d_out, int out_size)
{
    const float* node_labels = (const float*)d_in[0];
    const int*   edges       = (const int*)d_in[1];
    const int*   elab        = (const int*)d_in[2];
    const int*   vg          = (const int*)d_in[3];
    const int*   vs          = (const int*)d_in[4];
    // d_in[5] = labels (unused); num_vars scalar may or may not be present at [6]
    int w = (n_in >= 20 && in_sizes[6] == 1) ? 7 : 6;
    const float* enc_W0  = (const float*)d_in[w + 0];
    const float* enc_b0  = (const float*)d_in[w + 1];
    const float* enc_W1  = (const float*)d_in[w + 2];
    const float* enc_b1  = (const float*)d_in[w + 3];
    const float* edge_emb= (const float*)d_in[w + 4];
    const float* mlp_W1  = (const float*)d_in[w + 5];
    const float* mlp_b1  = (const float*)d_in[w + 6];
    const float* mlp_W2  = (const float*)d_in[w + 7];
    const float* mlp_b2  = (const float*)d_in[w + 8];
    const float* dec_W0  = (const float*)d_in[w + 9];
    const float* dec_b0  = (const float*)d_in[w + 10];
    const float* dec_Wl  = (const float*)d_in[w + 11];
    const float* dec_bl  = (const float*)d_in[w + 12];
    float* out = (float*)d_out;

    float *h, *t, *acc, *PQ, *R, *vsum, *vcnt, *vrep;
    cudaGetSymbolAddress((void**)&h,    g_h);
    cudaGetSymbolAddress((void**)&t,    g_t);
    cudaGetSymbolAddress((void**)&acc,  g_acc);
    cudaGetSymbolAddress((void**)&PQ,   g_PQ);
    cudaGetSymbolAddress((void**)&R,    g_R);
    cudaGetSymbolAddress((void**)&vsum, g_vsum);
    cudaGetSymbolAddress((void**)&vcnt, g_vcnt);
    cudaGetSymbolAddress((void**)&vrep, g_vrep);

    int nsm = 148;
    cudaDeviceGetAttribute(&nsm, cudaDevAttrMultiProcessorCount, 0);

    const int EDGE_SMEM = (256 * 128 + 256 * 33) * (int)sizeof(float);
    cudaFuncSetAttribute(edge_kernel, cudaFuncAttributeMaxDynamicSharedMemorySize, EDGE_SMEM);

    // per-etype bias tables for all 8 layers
    r_kernel<<<dim3(N_ETYPES, N_LAYERS), 256>>>(edge_emb, mlp_W1, mlp_b1, R);

    // encoder: t = relu(X@W0+b0); h = t@W1+b1
    launch_sgemm(node_labels, IN_DIM, enc_W0, D, enc_b0, t, D, N_NODES, D, IN_DIM, 1);
    launch_sgemm(t, D, enc_W1, D, enc_b1, h, D, N_NODES, D, D, 0);

    for (int l = 0; l < N_LAYERS; l++) {
        const float* W1l = mlp_W1 + (size_t)l * 384 * 256;
        // P = h @ W1[0:128,:]  -> PQ[:,0:256] ; Q = h @ W1[128:256,:] -> PQ[:,256:512]
        launch_sgemm(h, D, W1l,             256, nullptr, PQ,       512, N_NODES, 256, D, 0);
        launch_sgemm(h, D, W1l + 128 * 256, 256, nullptr, PQ + 256, 512, N_NODES, 256, D, 0);
        zero_kernel<<<(N_NODES * D + 255) / 256, 256>>>(acc, N_NODES * D);
        edge_kernel<<<nsm, 256, EDGE_SMEM>>>(edges, elab,
                                             R + (size_t)l * N_ETYPES * 256,
                                             mlp_W2 + (size_t)l * 256 * 128,
                                             mlp_b2 + (size_t)l * 128);
        gelu_kernel<<<(N_NODES * D + 255) / 256, 256>>>(acc, h, N_NODES * D);
    }

    // readout: scatter-mean into variables
    zero_kernel<<<(N_VARS * D + 255) / 256, 256>>>(vsum, N_VARS * D);
    zero_kernel<<<(N_VARS + 255) / 256, 256>>>(vcnt, N_VARS);
    scatter_kernel<<<(N_MENTIONS * D + 255) / 256, 256>>>(vg, vs);
    vrep_kernel<<<(N_VARS * D + 255) / 256, 256>>>();

    // decoder
    launch_sgemm(vrep, D, dec_W0, D, dec_b0, t, D, N_VARS, D, D, 1);
    launch_sgemm(t, D, dec_Wl, OUT_DIM, dec_bl, out, OUT_DIM, N_VARS, OUT_DIM, D, 0);
}

// round 2
// speedup vs baseline: 2.3770x; 2.3770x over previous
#include <cuda_runtime.h>
#include <math.h>

#define N_NODES   50000
#define N_EDGES   600000
#define IN_DIM    64
#define D         128
#define N_LAYERS  8
#define N_ETYPES  44
#define N_MENTIONS 100000
#define N_VARS    20000
#define OUT_DIM   100

// ---------------- scratch (device globals; no allocation allowed) ----------------
__device__ float g_h[N_NODES * D];
__device__ float g_t[N_NODES * D];
__device__ float g_acc[N_NODES * D];
__device__ float g_PQ[N_NODES * 512];       // [n][0:256]=P (dst part), [n][256:512]=Q (src part)
__device__ float g_R[N_LAYERS * N_ETYPES * 256];
__device__ float g_vsum[N_VARS * D];
__device__ float g_vcnt[N_VARS];
__device__ float g_vrep[N_VARS * D];

// ---------------- generic tiled SGEMM: C = act(A@B + bias) ----------------
__global__ void sgemm_kernel(const float* __restrict__ A, int lda,
                             const float* __restrict__ B, int ldb,
                             const float* __restrict__ bias,
                             float* __restrict__ C, int ldc,
                             int M, int N, int K, int act)
{
    __shared__ __align__(16) float As[16][68];
    __shared__ __align__(16) float Bs[16][64];
    const int tid = threadIdx.x;
    const int m0 = blockIdx.y * 64, n0 = blockIdx.x * 64;
    const int ty = tid >> 4, tx = tid & 15;

    float acc[4][4];
#pragma unroll
    for (int i = 0; i < 4; i++)
#pragma unroll
        for (int j = 0; j < 4; j++) acc[i][j] = 0.f;

    for (int k0 = 0; k0 < K; k0 += 16) {
        {
            int r = tid >> 4, c = tid & 15;
#pragma unroll
            for (int p = 0; p < 4; p++) {
                int m = m0 + p * 16 + r;
                As[c][p * 16 + r] = (m < M) ? A[(size_t)m * lda + k0 + c] : 0.f;
            }
        }
        {
            int r = tid >> 6, c = tid & 63;
#pragma unroll
            for (int p = 0; p < 4; p++) {
                int k = k0 + p * 4 + r, n = n0 + c;
                Bs[p * 4 + r][c] = (n < N) ? B[(size_t)k * ldb + n] : 0.f;
            }
        }
        __syncthreads();
#pragma unroll
        for (int kk = 0; kk < 16; kk++) {
            float4 a4 = *(const float4*)&As[kk][ty * 4];
            float4 b4 = *(const float4*)&Bs[kk][tx * 4];
            acc[0][0] += a4.x * b4.x; acc[0][1] += a4.x * b4.y; acc[0][2] += a4.x * b4.z; acc[0][3] += a4.x * b4.w;
            acc[1][0] += a4.y * b4.x; acc[1][1] += a4.y * b4.y; acc[1][2] += a4.y * b4.z; acc[1][3] += a4.y * b4.w;
            acc[2][0] += a4.z * b4.x; acc[2][1] += a4.z * b4.y; acc[2][2] += a4.z * b4.z; acc[2][3] += a4.z * b4.w;
            acc[3][0] += a4.w * b4.x; acc[3][1] += a4.w * b4.y; acc[3][2] += a4.w * b4.z; acc[3][3] += a4.w * b4.w;
        }
        __syncthreads();
    }
#pragma unroll
    for (int i = 0; i < 4; i++) {
        int m = m0 + ty * 4 + i;
        if (m >= M) continue;
#pragma unroll
        for (int j = 0; j < 4; j++) {
            int n = n0 + tx * 4 + j;
            if (n >= N) continue;
            float v = acc[i][j] + (bias ? bias[n] : 0.f);
            if (act == 1) v = fmaxf(v, 0.f);
            C[(size_t)m * ldc + n] = v;
        }
    }
}

// ---------------- per-etype R table ----------------
__global__ void r_kernel(const float* __restrict__ edge_emb,
                         const float* __restrict__ mlp_W1,
                         const float* __restrict__ mlp_b1,
                         float* __restrict__ R)
{
    int l = blockIdx.y, e = blockIdx.x, j = threadIdx.x;
    __shared__ float emb[128];
    if (j < 128) emb[j] = edge_emb[(l * N_ETYPES + e) * 128 + j];
    __syncthreads();
    const float* W = mlp_W1 + ((size_t)l * 384 + 256) * 256;
    float s = mlp_b1[l * 256 + j];
#pragma unroll 8
    for (int k = 0; k < 128; k++) s += emb[k] * W[k * 256 + j];
    R[((size_t)l * N_ETYPES + e) * 256 + j] = s;
}

// ---------------- warp-specialized edge kernel ----------------
// 512 threads: warps 0-7 consumers (GEMM + atomics), warps 8-15 producers (gather Z).
// Double-buffered Z [256][36] per buffer (stride 36 -> LDS.128-aligned, broadcast reads).
#define TE 32
#define ZSTRIDE 36

__global__ __launch_bounds__(512, 1)
void edge_kernel(const int* __restrict__ edges,
                 const int* __restrict__ elab,
                 const float* __restrict__ Rl,    // [44][256]
                 const float* __restrict__ W2l,   // [256][128]
                 const float* __restrict__ b2l)   // [128]
{
    extern __shared__ __align__(16) float sm[];
    float* W2s = sm;                      // 256*128 floats
    float* Zb  = sm + 256 * 128;          // 2 * 256*36 floats
    __shared__ int s_src[2][TE], s_dst[2][TE], s_lab[2][TE];

    const int tid = threadIdx.x;
    const bool producer = (tid >= 256);

    // cooperative W2 load (all 512 threads)
    {
        const float4* src = (const float4*)W2l;
        float4* dst = (float4*)W2s;
#pragma unroll
        for (int i = tid; i < 256 * 128 / 4; i += 512) dst[i] = src[i];
    }

    const int step = gridDim.x * TE;
    int base = blockIdx.x * TE;

    if (producer) {
        // ---------------- PRODUCER ----------------
        const int pk = tid - 256;         // owns k = pk in [0,256)
        // prologue: fill buffer 0 with tile 'base'
        {
            if (pk < TE) {
                s_src[0][pk] = edges[base + pk];
                s_dst[0][pk] = edges[N_EDGES + base + pk];
                s_lab[0][pk] = elab[base + pk];
            }
            asm volatile("bar.sync 1, 256;" ::: "memory");
            float* Zp = Zb + pk * ZSTRIDE;
#pragma unroll
            for (int e0 = 0; e0 < TE; e0 += 4) {
                float4 z;
                {
                    int dn = s_dst[0][e0+0], sn = s_src[0][e0+0], lb = s_lab[0][e0+0];
                    z.x = fmaxf(g_PQ[dn * 512 + pk] + g_PQ[sn * 512 + 256 + pk] + Rl[lb * 256 + pk], 0.f);
                }
                {
                    int dn = s_dst[0][e0+1], sn = s_src[0][e0+1], lb = s_lab[0][e0+1];
                    z.y = fmaxf(g_PQ[dn * 512 + pk] + g_PQ[sn * 512 + 256 + pk] + Rl[lb * 256 + pk], 0.f);
                }
                {
                    int dn = s_dst[0][e0+2], sn = s_src[0][e0+2], lb = s_lab[0][e0+2];
                    z.z = fmaxf(g_PQ[dn * 512 + pk] + g_PQ[sn * 512 + 256 + pk] + Rl[lb * 256 + pk], 0.f);
                }
                {
                    int dn = s_dst[0][e0+3], sn = s_src[0][e0+3], lb = s_lab[0][e0+3];
                    z.w = fmaxf(g_PQ[dn * 512 + pk] + g_PQ[sn * 512 + 256 + pk] + Rl[lb * 256 + pk], 0.f);
                }
                *(float4*)(Zp + e0) = z;
            }
        }
        __syncthreads();   // buffer 0 ready

        int p = 0;
        for (int t = base; t < N_EDGES; t += step, p ^= 1) {
            int nt = t + step;
            if (nt < N_EDGES) {
                int np = p ^ 1;
                if (pk < TE) {
                    s_src[np][pk] = edges[nt + pk];
                    s_dst[np][pk] = edges[N_EDGES + nt + pk];
                    s_lab[np][pk] = elab[nt + pk];
                }
                asm volatile("bar.sync 1, 256;" ::: "memory");
                float* Zp = Zb + np * 256 * ZSTRIDE + pk * ZSTRIDE;
#pragma unroll
                for (int e0 = 0; e0 < TE; e0 += 4) {
                    float4 z;
                    {
                        int dn = s_dst[np][e0+0], sn = s_src[np][e0+0], lb = s_lab[np][e0+0];
                        z.x = fmaxf(g_PQ[dn * 512 + pk] + g_PQ[sn * 512 + 256 + pk] + Rl[lb * 256 + pk], 0.f);
                    }
                    {
                        int dn = s_dst[np][e0+1], sn = s_src[np][e0+1], lb = s_lab[np][e0+1];
                        z.y = fmaxf(g_PQ[dn * 512 + pk] + g_PQ[sn * 512 + 256 + pk] + Rl[lb * 256 + pk], 0.f);
                    }
                    {
                        int dn = s_dst[np][e0+2], sn = s_src[np][e0+2], lb = s_lab[np][e0+2];
                        z.z = fmaxf(g_PQ[dn * 512 + pk] + g_PQ[sn * 512 + 256 + pk] + Rl[lb * 256 + pk], 0.f);
                    }
                    {
                        int dn = s_dst[np][e0+3], sn = s_src[np][e0+3], lb = s_lab[np][e0+3];
                        z.w = fmaxf(g_PQ[dn * 512 + pk] + g_PQ[sn * 512 + 256 + pk] + Rl[lb * 256 + pk], 0.f);
                    }
                    *(float4*)(Zp + e0) = z;
                }
            }
            __syncthreads();
        }
    } else {
        // ---------------- CONSUMER ----------------
        const int eg = tid >> 5;          // warp id: edges eg*4..eg*4+3
        const int jg = tid & 31;          // channels jg*4..jg*4+3
        const float bb0 = b2l[jg * 4 + 0], bb1 = b2l[jg * 4 + 1];
        const float bb2 = b2l[jg * 4 + 2], bb3 = b2l[jg * 4 + 3];

        __syncthreads();   // wait for prologue buffer 0

        int p = 0;
        for (int t = base; t < N_EDGES; t += step, p ^= 1) {
            float a[4][4];
#pragma unroll
            for (int i = 0; i < 4; i++) { a[i][0] = bb0; a[i][1] = bb1; a[i][2] = bb2; a[i][3] = bb3; }
            const float* Zc = Zb + p * 256 * ZSTRIDE + eg * 4;
            const float* Wc = W2s + jg * 4;
#pragma unroll 8
            for (int k = 0; k < 256; k++) {
                float4 w = *(const float4*)(Wc + k * 128);
                float4 z = *(const float4*)(Zc + k * ZSTRIDE);    // broadcast across warp
                a[0][0] += z.x * w.x; a[0][1] += z.x * w.y; a[0][2] += z.x * w.z; a[0][3] += z.x * w.w;
                a[1][0] += z.y * w.x; a[1][1] += z.y * w.y; a[1][2] += z.y * w.z; a[1][3] += z.y * w.w;
                a[2][0] += z.z * w.x; a[2][1] += z.z * w.y; a[2][2] += z.z * w.z; a[2][3] += z.z * w.w;
                a[3][0] += z.w * w.x; a[3][1] += z.w * w.y; a[3][2] += z.w * w.z; a[3][3] += z.w * w.w;
            }
#pragma unroll
            for (int i = 0; i < 4; i++) {
                int dn = s_dst[p][eg * 4 + i];
                float* ptr = g_acc + dn * 128 + jg * 4;
                atomicAdd(ptr + 0, a[i][0]);
                atomicAdd(ptr + 1, a[i][1]);
                atomicAdd(ptr + 2, a[i][2]);
                atomicAdd(ptr + 3, a[i][3]);
            }
            __syncthreads();
        }
    }
}

// ---------------- small elementwise kernels ----------------
__global__ void zero_kernel(float* p, int n) {
    int i = blockIdx.x * blockDim.x + threadIdx.x;
    if (i < n) p[i] = 0.f;
}

__global__ void gelu_kernel(const float* __restrict__ in, float* __restrict__ out, int n) {
    int i = blockIdx.x * blockDim.x + threadIdx.x;
    if (i < n) {
        float x = in[i];
        out[i] = 0.5f * x * (1.f + erff(x * 0.70710678118654752f));
    }
}

__global__ void scatter_kernel(const int* __restrict__ vg, const int* __restrict__ vs) {
    int i = blockIdx.x * blockDim.x + threadIdx.x;
    if (i >= N_MENTIONS * D) return;
    int m = i >> 7, c = i & 127;
    int v = vs[m], n = vg[m];
    atomicAdd(&g_vsum[v * D + c], g_h[n * D + c]);
    if (c == 0) atomicAdd(&g_vcnt[v], 1.0f);
}

__global__ void vrep_kernel() {
    int i = blockIdx.x * blockDim.x + threadIdx.x;
    if (i >= N_VARS * D) return;
    int v = i >> 7;
    g_vrep[i] = g_vsum[i] / fmaxf(g_vcnt[v], 1.0f);
}

// ---------------- host ----------------
static void launch_sgemm(const float* A, int lda, const float* B, int ldb, const float* bias,
                         float* C, int ldc, int M, int N, int K, int act)
{
    dim3 grid((N + 63) / 64, (M + 63) / 64);
    sgemm_kernel<<<grid, 256>>>(A, lda, B, ldb, bias, C, ldc, M, N, K, act);
}

extern "C" void kernel_launch(void* const* d_in, const int* in_sizes, int n_in,
                              void* d_out, int out_size)
{
    const float* node_labels = (const float*)d_in[0];
    const int*   edges       = (const int*)d_in[1];
    const int*   elab        = (const int*)d_in[2];
    const int*   vg          = (const int*)d_in[3];
    const int*   vs          = (const int*)d_in[4];
    int w = (n_in >= 20 && in_sizes[6] == 1) ? 7 : 6;
    const float* enc_W0  = (const float*)d_in[w + 0];
    const float* enc_b0  = (const float*)d_in[w + 1];
    const float* enc_W1  = (const float*)d_in[w + 2];
    const float* enc_b1  = (const float*)d_in[w + 3];
    const float* edge_emb= (const float*)d_in[w + 4];
    const float* mlp_W1  = (const float*)d_in[w + 5];
    const float* mlp_b1  = (const float*)d_in[w + 6];
    const float* mlp_W2  = (const float*)d_in[w + 7];
    const float* mlp_b2  = (const float*)d_in[w + 8];
    const float* dec_W0  = (const float*)d_in[w + 9];
    const float* dec_b0  = (const float*)d_in[w + 10];
    const float* dec_Wl  = (const float*)d_in[w + 11];
    const float* dec_bl  = (const float*)d_in[w + 12];
    float* out = (float*)d_out;

    float *h, *t, *acc, *PQ, *R, *vsum, *vcnt, *vrep;
    cudaGetSymbolAddress((void**)&h,    g_h);
    cudaGetSymbolAddress((void**)&t,    g_t);
    cudaGetSymbolAddress((void**)&acc,  g_acc);
    cudaGetSymbolAddress((void**)&PQ,   g_PQ);
    cudaGetSymbolAddress((void**)&R,    g_R);
    cudaGetSymbolAddress((void**)&vsum, g_vsum);
    cudaGetSymbolAddress((void**)&vcnt, g_vcnt);
    cudaGetSymbolAddress((void**)&vrep, g_vrep);

    int nsm = 148;
    cudaDeviceGetAttribute(&nsm, cudaDevAttrMultiProcessorCount, 0);

    const int EDGE_SMEM = (256 * 128 + 2 * 256 * ZSTRIDE) * (int)sizeof(float);
    cudaFuncSetAttribute(edge_kernel, cudaFuncAttributeMaxDynamicSharedMemorySize, EDGE_SMEM);

    r_kernel<<<dim3(N_ETYPES, N_LAYERS), 256>>>(edge_emb, mlp_W1, mlp_b1, R);

    // encoder
    launch_sgemm(node_labels, IN_DIM, enc_W0, D, enc_b0, t, D, N_NODES, D, IN_DIM, 1);
    launch_sgemm(t, D, enc_W1, D, enc_b1, h, D, N_NODES, D, D, 0);

    for (int l = 0; l < N_LAYERS; l++) {
        const float* W1l = mlp_W1 + (size_t)l * 384 * 256;
        launch_sgemm(h, D, W1l,             256, nullptr, PQ,       512, N_NODES, 256, D, 0);
        launch_sgemm(h, D, W1l + 128 * 256, 256, nullptr, PQ + 256, 512, N_NODES, 256, D, 0);
        zero_kernel<<<(N_NODES * D + 255) / 256, 256>>>(acc, N_NODES * D);
        edge_kernel<<<nsm, 512, EDGE_SMEM>>>(edges, elab,
                                             R + (size_t)l * N_ETYPES * 256,
                                             mlp_W2 + (size_t)l * 256 * 128,
                                             mlp_b2 + (size_t)l * 128);
        gelu_kernel<<<(N_NODES * D + 255) / 256, 256>>>(acc, h, N_NODES * D);
    }

    // readout
    zero_kernel<<<(N_VARS * D + 255) / 256, 256>>>(vsum, N_VARS * D);
    zero_kernel<<<(N_VARS + 255) / 256, 256>>>(vcnt, N_VARS);
    scatter_kernel<<<(N_MENTIONS * D + 255) / 256, 256>>>(vg, vs);
    vrep_kernel<<<(N_VARS * D + 255) / 256, 256>>>();

    // decoder
    launch_sgemm(vrep, D, dec_W0, D, dec_b0, t, D, N_VARS, D, D, 1);
    launch_sgemm(t, D, dec_Wl, OUT_DIM, dec_bl, out, OUT_DIM, N_VARS, OUT_DIM, D, 0);
}